// round 12
// baseline (speedup 1.0000x reference)
#include <cuda_runtime.h>
#include <cuda_fp16.h>
#include <cstdint>

#define SEQ 512
#define CHAN 512
#define NH 8
#define BATCH 32
#define NPH 2048          // n per head = 32 batch * 64 ch
#define TILE_B 16384      // one chunk tile: 128 rows x 128 bytes (swizzled)
#define NSTAGE 3
#define STAGE_BYTES (2 * TILE_B)
#define MBAR_OFF (NSTAGE * STAGE_BYTES)
#define GEMM_SMEM (MBAR_OFF + 64)

// ---------------- device globals (scratch; no allocs allowed) ----------------
__device__ __align__(16) unsigned char g_wh[NH * 4 * 8 * TILE_B];      // 4MB swizzled tiles
__device__ __align__(16) unsigned char g_xh[NH * 16 * 8 * TILE_B];     // 16MB swizzled tiles
__device__ __align__(16) float g_outT[NH * NPH * SEQ];                 // [h][n][p] 33.5MB

// ---------------- helpers ----------------
__device__ __forceinline__ uint32_t smem_u32(const void* p) {
    uint32_t a;
    asm("{ .reg .u64 t; cvta.to.shared.u64 t, %1; cvt.u32.u64 %0, t; }" : "=r"(a) : "l"(p));
    return a;
}
__device__ __forceinline__ void ldsm_x4(uint32_t r[4], uint32_t addr) {
    asm volatile("ldmatrix.sync.aligned.m8n8.x4.shared.b16 {%0,%1,%2,%3}, [%4];"
                 : "=r"(r[0]), "=r"(r[1]), "=r"(r[2]), "=r"(r[3]) : "r"(addr));
}
__device__ __forceinline__ void mma_fp16(float c[4], const uint32_t a[4],
                                         const uint32_t* b) {
    asm volatile("mma.sync.aligned.m16n8k16.row.col.f32.f16.f16.f32 "
                 "{%0,%1,%2,%3}, {%4,%5,%6,%7}, {%8,%9}, {%0,%1,%2,%3};"
                 : "+f"(c[0]), "+f"(c[1]), "+f"(c[2]), "+f"(c[3])
                 : "r"(a[0]), "r"(a[1]), "r"(a[2]), "r"(a[3]), "r"(b[0]), "r"(b[1]));
}
#define MB_INIT(mb, cnt) \
    asm volatile("mbarrier.init.shared.b64 [%0], %1;" \
                 :: "r"((uint32_t)(mb)), "r"((uint32_t)(cnt)) : "memory")
#define MB_EXPECT_TX(mb, bytes) \
    asm volatile("mbarrier.arrive.expect_tx.shared.b64 _, [%0], %1;" \
                 :: "r"((uint32_t)(mb)), "r"((uint32_t)(bytes)) : "memory")
#define MB_WAIT_PARITY(mb, par) do {                                            \
    uint32_t _m = (uint32_t)(mb), _p = (uint32_t)(par), _d;                     \
    asm volatile("{\n\t.reg .pred p;\n\t"                                       \
        "mbarrier.try_wait.parity.acquire.cta.shared::cta.b64 p, [%1], %2;\n\t" \
        "selp.b32 %0, 1, 0, p;\n\t}" : "=r"(_d) : "r"(_m), "r"(_p) : "memory"); \
    if (!_d) {                                                                  \
        asm volatile("{\n\t.reg .pred P1;\n\t"                                  \
            "WL_%=:\n\t"                                                        \
            "mbarrier.try_wait.parity.acquire.cta.shared::cta.b64 P1, [%0], %1, 0x989680;\n\t" \
            "@P1 bra.uni WD_%=;\n\t"                                            \
            "bra.uni WL_%=;\n\t"                                                \
            "WD_%=:\n\t}" :: "r"(_m), "r"(_p) : "memory");                      \
    }                                                                           \
} while (0)
#define CP_BULK(dst, src, sz, mb) \
    asm volatile("cp.async.bulk.shared::cluster.global.mbarrier::complete_tx::bytes " \
                 "[%0], [%1], %2, [%3];" \
                 :: "r"((uint32_t)(dst)), "l"(src), "r"((uint32_t)(sz)), \
                    "r"((uint32_t)(mb)) : "memory")

// swizzled byte offset of granule (row, c16) inside a 16KB tile
__device__ __forceinline__ int sw_off(int row, int c16) {
    return (row * 8 + (c16 ^ (row & 7))) * 16;
}

__device__ __forceinline__ int delta_idx(int pp, int pr) {
    int d0 = (pp - pr) & 7;
    int d1 = ((pp >> 3) - (pr >> 3)) & 7;
    int d2 = ((pp >> 6) - (pr >> 6)) & 7;
    return (d2 << 6) | (d1 << 3) | d0;
}

// ---------------- kernel 1: fused wtab + W -> blocked swizzled fp16 tiles ----------------
// 1024 blocks x 256 threads; blocks [h*128, (h+1)*128) handle head h.
__global__ void wsplit_kernel(const float* __restrict__ basis,
                              const float* __restrict__ kern) {
    __shared__ float sw[SEQ];       // w column for this block's head
    const int t = threadIdx.x;
    const int gid = blockIdx.x * 256 + t;   // 262144 granules
    const int h = gid >> 15;

    // compute w[delta] = basis[delta,:] @ kern[:,h]  (2 entries per thread)
#pragma unroll
    for (int rep = 0; rep < 2; rep++) {
        int e = t + rep * 256;
        float acc = 0.f;
#pragma unroll
        for (int s = 0; s < 24; s++)
            acc = fmaf(basis[e * 24 + s], kern[s * NH + h], acc);
        sw[e] = acc;
    }
    __syncthreads();

    const int c16 = gid & 7;
    const int row = (gid >> 3) & 127;
    const int ck  = (gid >> 10) & 7;
    const int pt  = (gid >> 13) & 3;
    const int p   = pt * 128 + row;
    __align__(16) __half hb[8];
#pragma unroll
    for (int j = 0; j < 8; j++) {
        int pp = ck * 64 + c16 * 8 + j;
        hb[j] = __float2half(sw[delta_idx(pp, p)]);
    }
    size_t off = ((size_t)((h * 4 + pt) * 8 + ck)) * TILE_B + sw_off(row, c16);
    *reinterpret_cast<uint4*>(g_wh + off) = *reinterpret_cast<uint4*>(hb);
}

// ---------------- kernel 2: x -> blocked swizzled fp16 tiles ----------------
__global__ __launch_bounds__(256) void xsplit_kernel(const float* __restrict__ x) {
    __shared__ float s[64][65];
    const int t = threadIdx.x;
    const int c0 = blockIdx.x * 64;
    const int p0 = blockIdx.y * 64;
    const int b  = blockIdx.z;
    const int ck = blockIdx.y;      // 64 p' per ck chunk

#pragma unroll
    for (int it = 0; it < 16; it++) {
        int prow = it * 4 + (t >> 6);
        int cl   = t & 63;
        s[prow][cl] = x[((size_t)(b * SEQ) + p0 + prow) * CHAN + c0 + cl];
    }
    __syncthreads();

    const int cl = t >> 2;          // c local
    const int pq = t & 3;           // 16 p' each
    const int c  = c0 + cl;
    const int h  = c & 7;
    const int ch = c >> 3;
    const int n  = b * 64 + ch;
    const int nt = n >> 7;
    const int nrow = n & 127;
    const size_t tb = ((size_t)((h * 16 + nt) * 8 + ck)) * TILE_B;

#pragma unroll
    for (int g = 0; g < 2; g++) {
        int c16 = pq * 2 + g;
        __align__(16) __half hb[8];
#pragma unroll
        for (int j = 0; j < 8; j++)
            hb[j] = __float2half(s[c16 * 8 + j][cl]);
        *reinterpret_cast<uint4*>(g_xh + tb + sw_off(nrow, c16)) =
            *reinterpret_cast<uint4*>(hb);
    }
}

// ---------------- kernel 3: fp16 HMMA GEMM, paired-chunk pipeline ----------------
// CTA: M=128 (p), N=128 (n), K=512 in 8 chunks, consumed in pairs (4 syncs).
__global__ __launch_bounds__(256, 2) void gemm_kernel() {
    extern __shared__ __align__(16) unsigned char sm[];
    const uint32_t sb0 = smem_u32(sm);
    const int tid  = threadIdx.x;
    const int lane = tid & 31;
    const int wid  = tid >> 5;
    const int wm   = wid & 3;       // m-group: 32 p rows
    const int wn   = wid >> 2;      // n-group: 64 n cols
    const int pt = blockIdx.x, nt = blockIdx.y, h = blockIdx.z;
    const int p0 = pt * 128;
    const int n0 = nt * 128;

    const unsigned char* gA = g_wh + ((size_t)((h * 4 + pt) * 8)) * TILE_B;
    const unsigned char* gB = g_xh + ((size_t)((h * 16 + nt) * 8)) * TILE_B;

    if (tid == 0) {
#pragma unroll
        for (int st = 0; st < NSTAGE; st++) MB_INIT(sb0 + MBAR_OFF + st * 8, 1);
    }
    __syncthreads();
    if (tid == 0) {
#pragma unroll
        for (int st = 0; st < NSTAGE; st++) {
            uint32_t mb = sb0 + MBAR_OFF + st * 8;
            MB_EXPECT_TX(mb, STAGE_BYTES);
            CP_BULK(sb0 + st * STAGE_BYTES,          gA + st * TILE_B, TILE_B, mb);
            CP_BULK(sb0 + st * STAGE_BYTES + TILE_B, gB + st * TILE_B, TILE_B, mb);
        }
    }

    // ldmatrix per-lane bases
    const int g  = lane >> 3, rr = lane & 7;
    const int a_row = wm * 32 + (g & 1) * 8 + rr;    // + mi*16
    const int a_cg  = g >> 1;                        // + 2*ks
    const int b_row = wn * 64 + (g >> 1) * 8 + rr;   // + bt*16
    const int b_cg  = g & 1;                         // + 2*ks

    float acc[2][8][4];
#pragma unroll
    for (int mi = 0; mi < 2; mi++)
#pragma unroll
        for (int ni = 0; ni < 8; ni++)
#pragma unroll
            for (int e = 0; e < 4; e++) acc[mi][ni][e] = 0.f;

    // consume one chunk from its stage buffer
    auto consume = [&](int ck) {
        const uint32_t mb = sb0 + MBAR_OFF + (ck % NSTAGE) * 8;
        MB_WAIT_PARITY(mb, (ck / NSTAGE) & 1);
        const uint32_t sb = sb0 + (ck % NSTAGE) * STAGE_BYTES;
#pragma unroll
        for (int ks = 0; ks < 4; ks++) {
            uint32_t Af[2][4], Bf[4][4];
#pragma unroll
            for (int mi = 0; mi < 2; mi++) {
                int row = a_row + mi * 16;
                int c16 = 2 * ks + a_cg;
                ldsm_x4(Af[mi], sb + (uint32_t)sw_off(row, c16));
            }
#pragma unroll
            for (int bt = 0; bt < 4; bt++) {
                int row = b_row + bt * 16;
                int c16 = 2 * ks + b_cg;
                ldsm_x4(Bf[bt], sb + TILE_B + (uint32_t)sw_off(row, c16));
            }
#pragma unroll
            for (int mi = 0; mi < 2; mi++)
#pragma unroll
                for (int ni = 0; ni < 8; ni++)
                    mma_fp16(acc[mi][ni], Af[mi], &Bf[ni >> 1][(ni & 1) * 2]);
        }
    };

#pragma unroll 1
    for (int pair = 0; pair < 4; pair++) {
        const int c0 = 2 * pair;
        consume(c0);
        consume(c0 + 1);
        __syncthreads();   // both stages of this pair fully consumed CTA-wide
        if (tid == 0) {
#pragma unroll
            for (int q = 0; q < 2; q++) {
                int cr = c0 + q + NSTAGE;          // refill chunk
                if (cr < 8) {
                    int st = cr % NSTAGE;          // == (c0+q) % NSTAGE (just consumed)
                    uint32_t mb = sb0 + MBAR_OFF + st * 8;
                    uint32_t sb = sb0 + st * STAGE_BYTES;
                    MB_EXPECT_TX(mb, STAGE_BYTES);
                    CP_BULK(sb,          gA + cr * TILE_B, TILE_B, mb);
                    CP_BULK(sb + TILE_B, gB + cr * TILE_B, TILE_B, mb);
                }
            }
        }
    }

    // ---- epilogue: smem transpose then coalesced 16B stores to g_outT[h][n][p] ----
    // (stage buffers fully consumed; sf = 128*132*4 = 67.5KB < MBAR_OFF)
    float* sf = reinterpret_cast<float*>(sm);   // [128 n][132 pad] fp32
    {
        const int prl = wm * 32 + (lane >> 2);
        const int nll = wn * 64 + 2 * (lane & 3);
#pragma unroll
        for (int mi = 0; mi < 2; mi++)
#pragma unroll
            for (int ni = 0; ni < 8; ni++)
#pragma unroll
                for (int e = 0; e < 4; e++) {
                    int p_l = prl + mi * 16 + (e >> 1) * 8;
                    int n_l = nll + ni * 8 + (e & 1);
                    sf[n_l * 132 + p_l] = acc[mi][ni][e];
                }
    }
    __syncthreads();
    {
        const int n_l  = tid >> 1;
        const int half = tid & 1;
        const float4* src = reinterpret_cast<const float4*>(sf + n_l * 132 + half * 64);
        float4* dst = reinterpret_cast<float4*>(
            g_outT + ((size_t)(h * NPH) + n0 + n_l) * SEQ + p0 + half * 64);
#pragma unroll
        for (int i = 0; i < 16; i++) dst[i] = src[i];
    }
}

// ---------------- kernel 4: outT[h][n][p] -> out[b][p][c] ----------------
__global__ __launch_bounds__(256) void untranspose_kernel(float* __restrict__ out) {
    __shared__ float s[16][513];
    const int t = threadIdx.x;
    const int p0 = blockIdx.x * 16;
    const int b  = blockIdx.y;
    const int k  = t & 15;      // p_local
    const int rr = t >> 4;      // 0..15

    for (int it = 0; it < 32; it++) {
        int c = it * 16 + rr;                     // output channel 0..511
        int h = c & 7, ch = c >> 3;
        s[k][c] = g_outT[((size_t)(h * NPH) + b * 64 + ch) * SEQ + p0 + k];
    }
    __syncthreads();
#pragma unroll
    for (int p = 0; p < 16; p++) {
        float2 v = make_float2(s[p][2 * t], s[p][2 * t + 1]);
        *reinterpret_cast<float2*>(
            &out[((size_t)(b * SEQ) + p0 + p) * CHAN + 2 * t]) = v;
    }
}

// ---------------- launch ----------------
extern "C" void kernel_launch(void* const* d_in, const int* in_sizes, int n_in,
                              void* d_out, int out_size) {
    const float* x = nullptr;
    const float* basis = nullptr;
    const float* kern = nullptr;
    for (int i = 0; i < n_in; i++) {
        if (in_sizes[i] == BATCH * SEQ * CHAN)      x     = (const float*)d_in[i];
        else if (in_sizes[i] == SEQ * 24)           basis = (const float*)d_in[i];
        else if (in_sizes[i] == 24 * NH)            kern  = (const float*)d_in[i];
    }
    float* out = (float*)d_out;

    cudaFuncSetAttribute(gemm_kernel,
                         cudaFuncAttributeMaxDynamicSharedMemorySize, GEMM_SMEM);

    wsplit_kernel<<<1024, 256>>>(basis, kern);
    xsplit_kernel<<<dim3(8, 8, 32), 256>>>(x);
    gemm_kernel<<<dim3(4, 16, NH), 256, GEMM_SMEM>>>();
    untranspose_kernel<<<dim3(32, 32), 256>>>(out);
}

// round 13
// speedup vs baseline: 1.0004x; 1.0004x over previous
#include <cuda_runtime.h>
#include <cuda_fp16.h>
#include <cstdint>

#define SEQ 512
#define CHAN 512
#define NH 8
#define BATCH 32
#define NPH 2048          // n per head = 32 batch * 64 ch
#define TILE_B 16384      // one chunk tile: 128 rows x 128 bytes (swizzled)
#define NSTAGE 3
#define STAGE_BYTES (2 * TILE_B)
#define MBAR_OFF (NSTAGE * STAGE_BYTES)
#define GEMM_SMEM (MBAR_OFF + 64)
#define UNT_SMEM (512 * 32 * 4)    // 64KB transpose tile

// ---------------- device globals (scratch; no allocs allowed) ----------------
__device__ __align__(16) unsigned char g_wh[NH * 4 * 8 * TILE_B];      // 4MB swizzled tiles
__device__ __align__(16) unsigned char g_xh[NH * 16 * 8 * TILE_B];     // 16MB swizzled tiles
__device__ __align__(16) float g_outT[NH * NPH * SEQ];                 // [h][n][p] 33.5MB

// ---------------- helpers ----------------
__device__ __forceinline__ uint32_t smem_u32(const void* p) {
    uint32_t a;
    asm("{ .reg .u64 t; cvta.to.shared.u64 t, %1; cvt.u32.u64 %0, t; }" : "=r"(a) : "l"(p));
    return a;
}
__device__ __forceinline__ void ldsm_x4(uint32_t r[4], uint32_t addr) {
    asm volatile("ldmatrix.sync.aligned.m8n8.x4.shared.b16 {%0,%1,%2,%3}, [%4];"
                 : "=r"(r[0]), "=r"(r[1]), "=r"(r[2]), "=r"(r[3]) : "r"(addr));
}
__device__ __forceinline__ void mma_fp16(float c[4], const uint32_t a[4],
                                         const uint32_t* b) {
    asm volatile("mma.sync.aligned.m16n8k16.row.col.f32.f16.f16.f32 "
                 "{%0,%1,%2,%3}, {%4,%5,%6,%7}, {%8,%9}, {%0,%1,%2,%3};"
                 : "+f"(c[0]), "+f"(c[1]), "+f"(c[2]), "+f"(c[3])
                 : "r"(a[0]), "r"(a[1]), "r"(a[2]), "r"(a[3]), "r"(b[0]), "r"(b[1]));
}
#define MB_INIT(mb, cnt) \
    asm volatile("mbarrier.init.shared.b64 [%0], %1;" \
                 :: "r"((uint32_t)(mb)), "r"((uint32_t)(cnt)) : "memory")
#define MB_EXPECT_TX(mb, bytes) \
    asm volatile("mbarrier.arrive.expect_tx.shared.b64 _, [%0], %1;" \
                 :: "r"((uint32_t)(mb)), "r"((uint32_t)(bytes)) : "memory")
#define MB_WAIT_PARITY(mb, par) do {                                            \
    uint32_t _m = (uint32_t)(mb), _p = (uint32_t)(par), _d;                     \
    asm volatile("{\n\t.reg .pred p;\n\t"                                       \
        "mbarrier.try_wait.parity.acquire.cta.shared::cta.b64 p, [%1], %2;\n\t" \
        "selp.b32 %0, 1, 0, p;\n\t}" : "=r"(_d) : "r"(_m), "r"(_p) : "memory"); \
    if (!_d) {                                                                  \
        asm volatile("{\n\t.reg .pred P1;\n\t"                                  \
            "WL_%=:\n\t"                                                        \
            "mbarrier.try_wait.parity.acquire.cta.shared::cta.b64 P1, [%0], %1, 0x989680;\n\t" \
            "@P1 bra.uni WD_%=;\n\t"                                            \
            "bra.uni WL_%=;\n\t"                                                \
            "WD_%=:\n\t}" :: "r"(_m), "r"(_p) : "memory");                      \
    }                                                                           \
} while (0)
#define CP_BULK(dst, src, sz, mb) \
    asm volatile("cp.async.bulk.shared::cluster.global.mbarrier::complete_tx::bytes " \
                 "[%0], [%1], %2, [%3];" \
                 :: "r"((uint32_t)(dst)), "l"(src), "r"((uint32_t)(sz)), \
                    "r"((uint32_t)(mb)) : "memory")

// swizzled byte offset of granule (row, c16) inside a 16KB tile
__device__ __forceinline__ int sw_off(int row, int c16) {
    return (row * 8 + (c16 ^ (row & 7))) * 16;
}

__device__ __forceinline__ int delta_idx(int pp, int pr) {
    int d0 = (pp - pr) & 7;
    int d1 = ((pp >> 3) - (pr >> 3)) & 7;
    int d2 = ((pp >> 6) - (pr >> 6)) & 7;
    return (d2 << 6) | (d1 << 3) | d0;
}

// ---------------- kernel 1: fused wtab + W -> blocked swizzled fp16 tiles ----------------
__global__ void wsplit_kernel(const float* __restrict__ basis,
                              const float* __restrict__ kern) {
    __shared__ float sw[SEQ];       // w column for this block's head
    const int t = threadIdx.x;
    const int gid = blockIdx.x * 256 + t;   // 262144 granules
    const int h = gid >> 15;

#pragma unroll
    for (int rep = 0; rep < 2; rep++) {
        int e = t + rep * 256;
        float acc = 0.f;
#pragma unroll
        for (int s = 0; s < 24; s++)
            acc = fmaf(basis[e * 24 + s], kern[s * NH + h], acc);
        sw[e] = acc;
    }
    __syncthreads();

    const int c16 = gid & 7;
    const int row = (gid >> 3) & 127;
    const int ck  = (gid >> 10) & 7;
    const int pt  = (gid >> 13) & 3;
    const int p   = pt * 128 + row;
    __align__(16) __half hb[8];
#pragma unroll
    for (int j = 0; j < 8; j++) {
        int pp = ck * 64 + c16 * 8 + j;
        hb[j] = __float2half(sw[delta_idx(pp, p)]);
    }
    size_t off = ((size_t)((h * 4 + pt) * 8 + ck)) * TILE_B + sw_off(row, c16);
    *reinterpret_cast<uint4*>(g_wh + off) = *reinterpret_cast<uint4*>(hb);
}

// ---------------- kernel 2: x -> blocked swizzled fp16 tiles ----------------
__global__ __launch_bounds__(256) void xsplit_kernel(const float* __restrict__ x) {
    __shared__ float s[64][65];
    const int t = threadIdx.x;
    const int c0 = blockIdx.x * 64;
    const int p0 = blockIdx.y * 64;
    const int b  = blockIdx.z;
    const int ck = blockIdx.y;      // 64 p' per ck chunk

#pragma unroll
    for (int it = 0; it < 16; it++) {
        int prow = it * 4 + (t >> 6);
        int cl   = t & 63;
        s[prow][cl] = x[((size_t)(b * SEQ) + p0 + prow) * CHAN + c0 + cl];
    }
    __syncthreads();

    const int cl = t >> 2;          // c local
    const int pq = t & 3;           // 16 p' each
    const int c  = c0 + cl;
    const int h  = c & 7;
    const int ch = c >> 3;
    const int n  = b * 64 + ch;
    const int nt = n >> 7;
    const int nrow = n & 127;
    const size_t tb = ((size_t)((h * 16 + nt) * 8 + ck)) * TILE_B;

#pragma unroll
    for (int g = 0; g < 2; g++) {
        int c16 = pq * 2 + g;
        __align__(16) __half hb[8];
#pragma unroll
        for (int j = 0; j < 8; j++)
            hb[j] = __float2half(s[c16 * 8 + j][cl]);
        *reinterpret_cast<uint4*>(g_xh + tb + sw_off(nrow, c16)) =
            *reinterpret_cast<uint4*>(hb);
    }
}

// ---------------- kernel 3: fp16 HMMA GEMM (R11 structure) + transposed epilogue ----
__global__ __launch_bounds__(256, 2) void gemm_kernel() {
    extern __shared__ __align__(16) unsigned char sm[];
    const uint32_t sb0 = smem_u32(sm);
    const int tid  = threadIdx.x;
    const int lane = tid & 31;
    const int wid  = tid >> 5;
    const int wm   = wid & 3;       // m-group: 32 p rows
    const int wn   = wid >> 2;      // n-group: 64 n cols
    const int pt = blockIdx.x, nt = blockIdx.y, h = blockIdx.z;
    const int p0 = pt * 128;
    const int n0 = nt * 128;

    const unsigned char* gA = g_wh + ((size_t)((h * 4 + pt) * 8)) * TILE_B;
    const unsigned char* gB = g_xh + ((size_t)((h * 16 + nt) * 8)) * TILE_B;

    if (tid == 0) {
#pragma unroll
        for (int st = 0; st < NSTAGE; st++) MB_INIT(sb0 + MBAR_OFF + st * 8, 1);
    }
    __syncthreads();
    if (tid == 0) {
#pragma unroll
        for (int st = 0; st < NSTAGE; st++) {
            uint32_t mb = sb0 + MBAR_OFF + st * 8;
            MB_EXPECT_TX(mb, STAGE_BYTES);
            CP_BULK(sb0 + st * STAGE_BYTES,          gA + st * TILE_B, TILE_B, mb);
            CP_BULK(sb0 + st * STAGE_BYTES + TILE_B, gB + st * TILE_B, TILE_B, mb);
        }
    }

    const int g  = lane >> 3, rr = lane & 7;
    const int a_row = wm * 32 + (g & 1) * 8 + rr;    // + mi*16
    const int a_cg  = g >> 1;                        // + 2*ks
    const int b_row = wn * 64 + (g >> 1) * 8 + rr;   // + bt*16
    const int b_cg  = g & 1;                         // + 2*ks

    float acc[2][8][4];
#pragma unroll
    for (int mi = 0; mi < 2; mi++)
#pragma unroll
        for (int ni = 0; ni < 8; ni++)
#pragma unroll
            for (int e = 0; e < 4; e++) acc[mi][ni][e] = 0.f;

    int st = 0, par = 0;
#pragma unroll 1
    for (int ck = 0; ck < 8; ck++) {
        const uint32_t mb = sb0 + MBAR_OFF + st * 8;
        MB_WAIT_PARITY(mb, par);
        const uint32_t sb = sb0 + st * STAGE_BYTES;

#pragma unroll
        for (int ks = 0; ks < 4; ks++) {
            uint32_t Af[2][4], Bf[4][4];
#pragma unroll
            for (int mi = 0; mi < 2; mi++) {
                int row = a_row + mi * 16;
                int c16 = 2 * ks + a_cg;
                ldsm_x4(Af[mi], sb + (uint32_t)sw_off(row, c16));
            }
#pragma unroll
            for (int bt = 0; bt < 4; bt++) {
                int row = b_row + bt * 16;
                int c16 = 2 * ks + b_cg;
                ldsm_x4(Bf[bt], sb + TILE_B + (uint32_t)sw_off(row, c16));
            }
#pragma unroll
            for (int mi = 0; mi < 2; mi++)
#pragma unroll
                for (int ni = 0; ni < 8; ni++)
                    mma_fp16(acc[mi][ni], Af[mi], &Bf[ni >> 1][(ni & 1) * 2]);
        }
        __syncthreads();   // all warps done with this stage buffer

        if (tid == 0 && ck + NSTAGE < 8) {
            MB_EXPECT_TX(mb, STAGE_BYTES);
            CP_BULK(sb,          gA + (ck + NSTAGE) * TILE_B, TILE_B, mb);
            CP_BULK(sb + TILE_B, gB + (ck + NSTAGE) * TILE_B, TILE_B, mb);
        }
        if (++st == NSTAGE) { st = 0; par ^= 1; }
    }

    // ---- epilogue: smem transpose then coalesced 16B stores to g_outT[h][n][p] ----
    float* sf = reinterpret_cast<float*>(sm);   // [128 n][132 pad] fp32 (67.5KB < MBAR_OFF)
    {
        const int prl = wm * 32 + (lane >> 2);
        const int nll = wn * 64 + 2 * (lane & 3);
#pragma unroll
        for (int mi = 0; mi < 2; mi++)
#pragma unroll
            for (int ni = 0; ni < 8; ni++)
#pragma unroll
                for (int e = 0; e < 4; e++) {
                    int p_l = prl + mi * 16 + (e >> 1) * 8;
                    int n_l = nll + ni * 8 + (e & 1);
                    sf[n_l * 132 + p_l] = acc[mi][ni][e];
                }
    }
    __syncthreads();
    {
        const int n_l  = tid >> 1;
        const int half = tid & 1;
        const float4* src = reinterpret_cast<const float4*>(sf + n_l * 132 + half * 64);
        float4* dst = reinterpret_cast<float4*>(
            g_outT + ((size_t)(h * NPH) + n0 + n_l) * SEQ + p0 + half * 64);
#pragma unroll
        for (int i = 0; i < 16; i++) dst[i] = src[i];
    }
}

// ---------------- kernel 4: outT[h][n][p] -> out[b][p][c], fully vectorized ----------------
// Block: 32 p x 512 c for one b. smem tile: [c][32 p] fp32, granule-XOR swizzled.
// granule q (4 p's) of row c stored at q' = q ^ ((c>>2)&7).
__global__ __launch_bounds__(256) void untranspose_kernel(float* __restrict__ out) {
    extern __shared__ __align__(16) float sf2[];
    const int t = threadIdx.x;
    const int p0 = blockIdx.x * 32;
    const int b  = blockIdx.y;

    // load: 16 LDG.128/thread, coalesced 128B rows of outT
#pragma unroll
    for (int i = 0; i < 16; i++) {
        int vid = t + i * 256;          // 4096 granules
        int c = vid >> 3, q = vid & 7;
        int h = c & 7, ch = c >> 3;
        float4 v = *reinterpret_cast<const float4*>(
            g_outT + ((size_t)(h * NPH) + b * 64 + ch) * SEQ + p0 + q * 4);
        int qs = q ^ ((c >> 2) & 7);
        *reinterpret_cast<float4*>(sf2 + c * 32 + qs * 4) = v;
    }
    __syncthreads();

    // store: thread owns 4c x 4p; 4 LDS.128 + register transpose + 4 STG.128
#pragma unroll
    for (int i = 0; i < 4; i++) {
        int vid = t + i * 256;          // 1024 tasks
        int cq = vid & 127, pq = vid >> 7;
        int c0 = cq * 4;
        int qs = pq ^ (cq & 7);         // (c0+j)>>2 == cq for j<4
        float4 v[4];
#pragma unroll
        for (int j = 0; j < 4; j++)
            v[j] = *reinterpret_cast<const float4*>(sf2 + (c0 + j) * 32 + qs * 4);
        const float* vf = reinterpret_cast<const float*>(v);
#pragma unroll
        for (int r = 0; r < 4; r++) {
            float4 o = make_float4(vf[0 * 4 + r], vf[1 * 4 + r],
                                   vf[2 * 4 + r], vf[3 * 4 + r]);
            *reinterpret_cast<float4*>(
                out + ((size_t)(b * SEQ) + p0 + pq * 4 + r) * CHAN + c0) = o;
        }
    }
}

// ---------------- launch ----------------
extern "C" void kernel_launch(void* const* d_in, const int* in_sizes, int n_in,
                              void* d_out, int out_size) {
    const float* x = nullptr;
    const float* basis = nullptr;
    const float* kern = nullptr;
    for (int i = 0; i < n_in; i++) {
        if (in_sizes[i] == BATCH * SEQ * CHAN)      x     = (const float*)d_in[i];
        else if (in_sizes[i] == SEQ * 24)           basis = (const float*)d_in[i];
        else if (in_sizes[i] == 24 * NH)            kern  = (const float*)d_in[i];
    }
    float* out = (float*)d_out;

    cudaFuncSetAttribute(gemm_kernel,
                         cudaFuncAttributeMaxDynamicSharedMemorySize, GEMM_SMEM);
    cudaFuncSetAttribute(untranspose_kernel,
                         cudaFuncAttributeMaxDynamicSharedMemorySize, UNT_SMEM);

    wsplit_kernel<<<1024, 256>>>(basis, kern);
    xsplit_kernel<<<dim3(8, 8, 32), 256>>>(x);
    gemm_kernel<<<dim3(4, 16, NH), 256, GEMM_SMEM>>>();
    untranspose_kernel<<<dim3(16, 32), 256, UNT_SMEM>>>(out);
}

// round 14
// speedup vs baseline: 1.1216x; 1.1212x over previous
#include <cuda_runtime.h>
#include <cuda_fp16.h>
#include <cstdint>

#define SEQ 512
#define CHAN 512
#define NH 8
#define BATCH 32
#define NPH 2048          // n per head = 32 batch * 64 ch
#define TILE_B 16384      // one chunk tile: 128 rows x 128 bytes (swizzled)
#define NSTAGE 3
#define STAGE_BYTES (2 * TILE_B)
#define MBAR_OFF (NSTAGE * STAGE_BYTES)
#define GEMM_SMEM (MBAR_OFF + 64)

// ---------------- device globals (scratch; no allocs allowed) ----------------
__device__ __align__(16) unsigned char g_wh[NH * 4 * 8 * TILE_B];      // 4MB swizzled tiles
__device__ __align__(16) unsigned char g_xh[NH * 16 * 8 * TILE_B];     // 16MB swizzled tiles
__device__ __align__(16) __half g_outT[NH * NPH * SEQ];                // [h][n][p] fp16 16.8MB

// ---------------- helpers ----------------
__device__ __forceinline__ uint32_t smem_u32(const void* p) {
    uint32_t a;
    asm("{ .reg .u64 t; cvta.to.shared.u64 t, %1; cvt.u32.u64 %0, t; }" : "=r"(a) : "l"(p));
    return a;
}
__device__ __forceinline__ void ldsm_x4(uint32_t r[4], uint32_t addr) {
    asm volatile("ldmatrix.sync.aligned.m8n8.x4.shared.b16 {%0,%1,%2,%3}, [%4];"
                 : "=r"(r[0]), "=r"(r[1]), "=r"(r[2]), "=r"(r[3]) : "r"(addr));
}
__device__ __forceinline__ void mma_fp16(float c[4], const uint32_t a[4],
                                         const uint32_t* b) {
    asm volatile("mma.sync.aligned.m16n8k16.row.col.f32.f16.f16.f32 "
                 "{%0,%1,%2,%3}, {%4,%5,%6,%7}, {%8,%9}, {%0,%1,%2,%3};"
                 : "+f"(c[0]), "+f"(c[1]), "+f"(c[2]), "+f"(c[3])
                 : "r"(a[0]), "r"(a[1]), "r"(a[2]), "r"(a[3]), "r"(b[0]), "r"(b[1]));
}
#define MB_INIT(mb, cnt) \
    asm volatile("mbarrier.init.shared.b64 [%0], %1;" \
                 :: "r"((uint32_t)(mb)), "r"((uint32_t)(cnt)) : "memory")
#define MB_EXPECT_TX(mb, bytes) \
    asm volatile("mbarrier.arrive.expect_tx.shared.b64 _, [%0], %1;" \
                 :: "r"((uint32_t)(mb)), "r"((uint32_t)(bytes)) : "memory")
#define MB_WAIT_PARITY(mb, par) do {                                            \
    uint32_t _m = (uint32_t)(mb), _p = (uint32_t)(par), _d;                     \
    asm volatile("{\n\t.reg .pred p;\n\t"                                       \
        "mbarrier.try_wait.parity.acquire.cta.shared::cta.b64 p, [%1], %2;\n\t" \
        "selp.b32 %0, 1, 0, p;\n\t}" : "=r"(_d) : "r"(_m), "r"(_p) : "memory"); \
    if (!_d) {                                                                  \
        asm volatile("{\n\t.reg .pred P1;\n\t"                                  \
            "WL_%=:\n\t"                                                        \
            "mbarrier.try_wait.parity.acquire.cta.shared::cta.b64 P1, [%0], %1, 0x989680;\n\t" \
            "@P1 bra.uni WD_%=;\n\t"                                            \
            "bra.uni WL_%=;\n\t"                                                \
            "WD_%=:\n\t}" :: "r"(_m), "r"(_p) : "memory");                      \
    }                                                                           \
} while (0)
#define CP_BULK(dst, src, sz, mb) \
    asm volatile("cp.async.bulk.shared::cluster.global.mbarrier::complete_tx::bytes " \
                 "[%0], [%1], %2, [%3];" \
                 :: "r"((uint32_t)(dst)), "l"(src), "r"((uint32_t)(sz)), \
                    "r"((uint32_t)(mb)) : "memory")

// swizzled byte offset of granule (row, c16) inside a 16KB tile
__device__ __forceinline__ int sw_off(int row, int c16) {
    return (row * 8 + (c16 ^ (row & 7))) * 16;
}

__device__ __forceinline__ int delta_idx(int pp, int pr) {
    int d0 = (pp - pr) & 7;
    int d1 = ((pp >> 3) - (pr >> 3)) & 7;
    int d2 = ((pp >> 6) - (pr >> 6)) & 7;
    return (d2 << 6) | (d1 << 3) | d0;
}

// ---------------- kernel 1: fused wtab + W -> blocked swizzled fp16 tiles ----------------
__global__ void wsplit_kernel(const float* __restrict__ basis,
                              const float* __restrict__ kern) {
    __shared__ float sw[SEQ];       // w column for this block's head
    const int t = threadIdx.x;
    const int gid = blockIdx.x * 256 + t;   // 262144 granules
    const int h = gid >> 15;

#pragma unroll
    for (int rep = 0; rep < 2; rep++) {
        int e = t + rep * 256;
        float acc = 0.f;
#pragma unroll
        for (int s = 0; s < 24; s++)
            acc = fmaf(basis[e * 24 + s], kern[s * NH + h], acc);
        sw[e] = acc;
    }
    __syncthreads();

    const int c16 = gid & 7;
    const int row = (gid >> 3) & 127;
    const int ck  = (gid >> 10) & 7;
    const int pt  = (gid >> 13) & 3;
    const int p   = pt * 128 + row;
    __align__(16) __half hb[8];
#pragma unroll
    for (int j = 0; j < 8; j++) {
        int pp = ck * 64 + c16 * 8 + j;
        hb[j] = __float2half(sw[delta_idx(pp, p)]);
    }
    size_t off = ((size_t)((h * 4 + pt) * 8 + ck)) * TILE_B + sw_off(row, c16);
    *reinterpret_cast<uint4*>(g_wh + off) = *reinterpret_cast<uint4*>(hb);
}

// ---------------- kernel 2: x -> blocked swizzled fp16 tiles ----------------
__global__ __launch_bounds__(256) void xsplit_kernel(const float* __restrict__ x) {
    __shared__ float s[64][65];
    const int t = threadIdx.x;
    const int c0 = blockIdx.x * 64;
    const int p0 = blockIdx.y * 64;
    const int b  = blockIdx.z;
    const int ck = blockIdx.y;      // 64 p' per ck chunk

#pragma unroll
    for (int it = 0; it < 16; it++) {
        int prow = it * 4 + (t >> 6);
        int cl   = t & 63;
        s[prow][cl] = x[((size_t)(b * SEQ) + p0 + prow) * CHAN + c0 + cl];
    }
    __syncthreads();

    const int cl = t >> 2;          // c local
    const int pq = t & 3;           // 16 p' each
    const int c  = c0 + cl;
    const int h  = c & 7;
    const int ch = c >> 3;
    const int n  = b * 64 + ch;
    const int nt = n >> 7;
    const int nrow = n & 127;
    const size_t tb = ((size_t)((h * 16 + nt) * 8 + ck)) * TILE_B;

#pragma unroll
    for (int g = 0; g < 2; g++) {
        int c16 = pq * 2 + g;
        __align__(16) __half hb[8];
#pragma unroll
        for (int j = 0; j < 8; j++)
            hb[j] = __float2half(s[c16 * 8 + j][cl]);
        *reinterpret_cast<uint4*>(g_xh + tb + sw_off(nrow, c16)) =
            *reinterpret_cast<uint4*>(hb);
    }
}

// ---------------- kernel 3: fp16 HMMA GEMM (R11 structure) + fp16 transposed epilogue ----
__global__ __launch_bounds__(256, 2) void gemm_kernel() {
    extern __shared__ __align__(16) unsigned char sm[];
    const uint32_t sb0 = smem_u32(sm);
    const int tid  = threadIdx.x;
    const int lane = tid & 31;
    const int wid  = tid >> 5;
    const int wm   = wid & 3;       // m-group: 32 p rows
    const int wn   = wid >> 2;      // n-group: 64 n cols
    const int pt = blockIdx.x, nt = blockIdx.y, h = blockIdx.z;
    const int p0 = pt * 128;
    const int n0 = nt * 128;

    const unsigned char* gA = g_wh + ((size_t)((h * 4 + pt) * 8)) * TILE_B;
    const unsigned char* gB = g_xh + ((size_t)((h * 16 + nt) * 8)) * TILE_B;

    if (tid == 0) {
#pragma unroll
        for (int st = 0; st < NSTAGE; st++) MB_INIT(sb0 + MBAR_OFF + st * 8, 1);
    }
    __syncthreads();
    if (tid == 0) {
#pragma unroll
        for (int st = 0; st < NSTAGE; st++) {
            uint32_t mb = sb0 + MBAR_OFF + st * 8;
            MB_EXPECT_TX(mb, STAGE_BYTES);
            CP_BULK(sb0 + st * STAGE_BYTES,          gA + st * TILE_B, TILE_B, mb);
            CP_BULK(sb0 + st * STAGE_BYTES + TILE_B, gB + st * TILE_B, TILE_B, mb);
        }
    }

    const int g  = lane >> 3, rr = lane & 7;
    const int a_row = wm * 32 + (g & 1) * 8 + rr;    // + mi*16
    const int a_cg  = g >> 1;                        // + 2*ks
    const int b_row = wn * 64 + (g >> 1) * 8 + rr;   // + bt*16
    const int b_cg  = g & 1;                         // + 2*ks

    float acc[2][8][4];
#pragma unroll
    for (int mi = 0; mi < 2; mi++)
#pragma unroll
        for (int ni = 0; ni < 8; ni++)
#pragma unroll
            for (int e = 0; e < 4; e++) acc[mi][ni][e] = 0.f;

    int st = 0, par = 0;
#pragma unroll 1
    for (int ck = 0; ck < 8; ck++) {
        const uint32_t mb = sb0 + MBAR_OFF + st * 8;
        MB_WAIT_PARITY(mb, par);
        const uint32_t sb = sb0 + st * STAGE_BYTES;

#pragma unroll
        for (int ks = 0; ks < 4; ks++) {
            uint32_t Af[2][4], Bf[4][4];
#pragma unroll
            for (int mi = 0; mi < 2; mi++) {
                int row = a_row + mi * 16;
                int c16 = 2 * ks + a_cg;
                ldsm_x4(Af[mi], sb + (uint32_t)sw_off(row, c16));
            }
#pragma unroll
            for (int bt = 0; bt < 4; bt++) {
                int row = b_row + bt * 16;
                int c16 = 2 * ks + b_cg;
                ldsm_x4(Bf[bt], sb + TILE_B + (uint32_t)sw_off(row, c16));
            }
#pragma unroll
            for (int mi = 0; mi < 2; mi++)
#pragma unroll
                for (int ni = 0; ni < 8; ni++)
                    mma_fp16(acc[mi][ni], Af[mi], &Bf[ni >> 1][(ni & 1) * 2]);
        }
        __syncthreads();   // all warps done with this stage buffer

        if (tid == 0 && ck + NSTAGE < 8) {
            MB_EXPECT_TX(mb, STAGE_BYTES);
            CP_BULK(sb,          gA + (ck + NSTAGE) * TILE_B, TILE_B, mb);
            CP_BULK(sb + TILE_B, gB + (ck + NSTAGE) * TILE_B, TILE_B, mb);
        }
        if (++st == NSTAGE) { st = 0; par ^= 1; }
    }

    // ---- epilogue: smem transpose then packed fp16 stores to g_outT[h][n][p] ----
    float* sf = reinterpret_cast<float*>(sm);   // [128 n][132 pad] fp32 (67.5KB < MBAR_OFF)
    {
        const int prl = wm * 32 + (lane >> 2);
        const int nll = wn * 64 + 2 * (lane & 3);
#pragma unroll
        for (int mi = 0; mi < 2; mi++)
#pragma unroll
            for (int ni = 0; ni < 8; ni++)
#pragma unroll
                for (int e = 0; e < 4; e++) {
                    int p_l = prl + mi * 16 + (e >> 1) * 8;
                    int n_l = nll + ni * 8 + (e & 1);
                    sf[n_l * 132 + p_l] = acc[mi][ni][e];
                }
    }
    __syncthreads();
    {
        const int n_l  = tid >> 1;
        const int half = tid & 1;
        const float* srcf = sf + n_l * 132 + half * 64;
        uint4* dst = reinterpret_cast<uint4*>(
            g_outT + ((size_t)(h * NPH) + n0 + n_l) * SEQ + p0 + half * 64);
#pragma unroll
        for (int i = 0; i < 8; i++) {
            float4 a = *reinterpret_cast<const float4*>(srcf + i * 8);
            float4 b4 = *reinterpret_cast<const float4*>(srcf + i * 8 + 4);
            __half2 h01 = __floats2half2_rn(a.x, a.y);
            __half2 h23 = __floats2half2_rn(a.z, a.w);
            __half2 h45 = __floats2half2_rn(b4.x, b4.y);
            __half2 h67 = __floats2half2_rn(b4.z, b4.w);
            uint4 pk;
            pk.x = *reinterpret_cast<uint32_t*>(&h01);
            pk.y = *reinterpret_cast<uint32_t*>(&h23);
            pk.z = *reinterpret_cast<uint32_t*>(&h45);
            pk.w = *reinterpret_cast<uint32_t*>(&h67);
            dst[i] = pk;
        }
    }
}

// ---------------- kernel 4: outT fp16 [h][n][p] -> out fp32 [b][p][c] ----------------
// Block tile: 64 p x 256 c, smem 32KB halves [256 c][64 p], XOR-granule swizzled.
__global__ __launch_bounds__(256) void untranspose_kernel(float* __restrict__ out) {
    __shared__ __align__(16) __half sh[256 * 64];   // 32KB
    const int t = threadIdx.x;
    const int p0 = blockIdx.x * 64;
    const int c0 = blockIdx.y * 256;
    const int b  = blockIdx.z;

    // load: 8 LDG.128/thread, coalesced 128B rows of outT; granule = 8 p halves
#pragma unroll
    for (int i = 0; i < 8; i++) {
        int vid = t + i * 256;          // 2048 granules
        int cl = vid >> 3, q = vid & 7;
        int c = c0 + cl;
        int h = c & 7, ch = c >> 3;
        uint4 v = *reinterpret_cast<const uint4*>(
            g_outT + ((size_t)(h * NPH) + b * 64 + ch) * SEQ + p0 + q * 8);
        int qs = q ^ ((cl >> 2) & 7);
        *reinterpret_cast<uint4*>(sh + cl * 64 + qs * 8) = v;
    }
    __syncthreads();

    // store: task = 4 c x 8 p; 4 LDS.128 + register transpose + 8 STG.128 (fp32)
#pragma unroll
    for (int i = 0; i < 2; i++) {
        int vid = t + i * 256;          // 512 tasks
        int cq = vid & 63, pq = vid >> 6;
        int qs = pq ^ (cq & 7);         // ((4cq+j)>>2)&7 == cq&7 for j<4
        uint4 v[4];
#pragma unroll
        for (int j = 0; j < 4; j++)
            v[j] = *reinterpret_cast<const uint4*>(sh + (4 * cq + j) * 64 + qs * 8);
        const __half* hv = reinterpret_cast<const __half*>(v);
#pragma unroll
        for (int p = 0; p < 8; p++) {
            float4 o = make_float4(__half2float(hv[0 * 8 + p]),
                                   __half2float(hv[1 * 8 + p]),
                                   __half2float(hv[2 * 8 + p]),
                                   __half2float(hv[3 * 8 + p]));
            *reinterpret_cast<float4*>(
                out + ((size_t)(b * SEQ) + p0 + pq * 8 + p) * CHAN + c0 + 4 * cq) = o;
        }
    }
}

// ---------------- launch ----------------
extern "C" void kernel_launch(void* const* d_in, const int* in_sizes, int n_in,
                              void* d_out, int out_size) {
    const float* x = nullptr;
    const float* basis = nullptr;
    const float* kern = nullptr;
    for (int i = 0; i < n_in; i++) {
        if (in_sizes[i] == BATCH * SEQ * CHAN)      x     = (const float*)d_in[i];
        else if (in_sizes[i] == SEQ * 24)           basis = (const float*)d_in[i];
        else if (in_sizes[i] == 24 * NH)            kern  = (const float*)d_in[i];
    }
    float* out = (float*)d_out;

    cudaFuncSetAttribute(gemm_kernel,
                         cudaFuncAttributeMaxDynamicSharedMemorySize, GEMM_SMEM);

    wsplit_kernel<<<1024, 256>>>(basis, kern);
    xsplit_kernel<<<dim3(8, 8, 32), 256>>>(x);
    gemm_kernel<<<dim3(4, 16, NH), 256, GEMM_SMEM>>>();
    untranspose_kernel<<<dim3(8, 2, 32), 256>>>(out);
}

// round 16
// speedup vs baseline: 1.1488x; 1.0242x over previous
#include <cuda_runtime.h>
#include <cuda_fp16.h>
#include <cstdint>

#define SEQ 512
#define CHAN 512
#define NH 8
#define BATCH 32
#define NPH 2048          // n per head = 32 batch * 64 ch
#define TILE_B 16384      // one chunk tile: 128 rows x 128 bytes (swizzled)
#define NSTAGE 3
#define STAGE_BYTES (2 * TILE_B)
#define MBAR_OFF (NSTAGE * STAGE_BYTES)
#define GEMM_SMEM (MBAR_OFF + 64)

// ---------------- device globals (scratch; no allocs allowed) ----------------
__device__ __align__(16) unsigned char g_wh[NH * 4 * 8 * TILE_B];      // 4MB swizzled tiles
__device__ __align__(16) unsigned char g_xh[NH * 16 * 8 * TILE_B];     // 16MB swizzled tiles
__device__ __align__(16) __half g_outT[NH * NPH * SEQ];                // [h][n][p] fp16 16.8MB

// ---------------- helpers ----------------
__device__ __forceinline__ uint32_t smem_u32(const void* p) {
    uint32_t a;
    asm("{ .reg .u64 t; cvta.to.shared.u64 t, %1; cvt.u32.u64 %0, t; }" : "=r"(a) : "l"(p));
    return a;
}
__device__ __forceinline__ void ldsm_x4(uint32_t r[4], uint32_t addr) {
    asm volatile("ldmatrix.sync.aligned.m8n8.x4.shared.b16 {%0,%1,%2,%3}, [%4];"
                 : "=r"(r[0]), "=r"(r[1]), "=r"(r[2]), "=r"(r[3]) : "r"(addr));
}
__device__ __forceinline__ void mma_fp16(float c[4], const uint32_t a[4],
                                         const uint32_t* b) {
    asm volatile("mma.sync.aligned.m16n8k16.row.col.f32.f16.f16.f32 "
                 "{%0,%1,%2,%3}, {%4,%5,%6,%7}, {%8,%9}, {%0,%1,%2,%3};"
                 : "+f"(c[0]), "+f"(c[1]), "+f"(c[2]), "+f"(c[3])
                 : "r"(a[0]), "r"(a[1]), "r"(a[2]), "r"(a[3]), "r"(b[0]), "r"(b[1]));
}
#define MB_INIT(mb, cnt) \
    asm volatile("mbarrier.init.shared.b64 [%0], %1;" \
                 :: "r"((uint32_t)(mb)), "r"((uint32_t)(cnt)) : "memory")
#define MB_EXPECT_TX(mb, bytes) \
    asm volatile("mbarrier.arrive.expect_tx.shared.b64 _, [%0], %1;" \
                 :: "r"((uint32_t)(mb)), "r"((uint32_t)(bytes)) : "memory")
#define MB_WAIT_PARITY(mb, par) do {                                            \
    uint32_t _m = (uint32_t)(mb), _p = (uint32_t)(par), _d;                     \
    asm volatile("{\n\t.reg .pred p;\n\t"                                       \
        "mbarrier.try_wait.parity.acquire.cta.shared::cta.b64 p, [%1], %2;\n\t" \
        "selp.b32 %0, 1, 0, p;\n\t}" : "=r"(_d) : "r"(_m), "r"(_p) : "memory"); \
    if (!_d) {                                                                  \
        asm volatile("{\n\t.reg .pred P1;\n\t"                                  \
            "WL_%=:\n\t"                                                        \
            "mbarrier.try_wait.parity.acquire.cta.shared::cta.b64 P1, [%0], %1, 0x989680;\n\t" \
            "@P1 bra.uni WD_%=;\n\t"                                            \
            "bra.uni WL_%=;\n\t"                                                \
            "WD_%=:\n\t}" :: "r"(_m), "r"(_p) : "memory");                      \
    }                                                                           \
} while (0)
#define CP_BULK(dst, src, sz, mb) \
    asm volatile("cp.async.bulk.shared::cluster.global.mbarrier::complete_tx::bytes " \
                 "[%0], [%1], %2, [%3];" \
                 :: "r"((uint32_t)(dst)), "l"(src), "r"((uint32_t)(sz)), \
                    "r"((uint32_t)(mb)) : "memory")

// swizzled byte offset of granule (row, c16) inside a 16KB tile
__device__ __forceinline__ int sw_off(int row, int c16) {
    return (row * 8 + (c16 ^ (row & 7))) * 16;
}

__device__ __forceinline__ int delta_idx(int pp, int pr) {
    int d0 = (pp - pr) & 7;
    int d1 = ((pp >> 3) - (pr >> 3)) & 7;
    int d2 = ((pp >> 6) - (pr >> 6)) & 7;
    return (d2 << 6) | (d1 << 3) | d0;
}

// ---------------- kernel 1: fused wtab + W -> blocked swizzled fp16 tiles ----------------
__global__ void wsplit_kernel(const float* __restrict__ basis,
                              const float* __restrict__ kern) {
    __shared__ float sw[SEQ];       // w column for this block's head
    const int t = threadIdx.x;
    const int gid = blockIdx.x * 256 + t;   // 262144 granules
    const int h = gid >> 15;

#pragma unroll
    for (int rep = 0; rep < 2; rep++) {
        int e = t + rep * 256;
        float acc = 0.f;
#pragma unroll
        for (int s = 0; s < 24; s++)
            acc = fmaf(basis[e * 24 + s], kern[s * NH + h], acc);
        sw[e] = acc;
    }
    __syncthreads();

    const int c16 = gid & 7;
    const int row = (gid >> 3) & 127;
    const int ck  = (gid >> 10) & 7;
    const int pt  = (gid >> 13) & 3;
    const int p   = pt * 128 + row;
    __align__(16) __half hb[8];
#pragma unroll
    for (int j = 0; j < 8; j++) {
        int pp = ck * 64 + c16 * 8 + j;
        hb[j] = __float2half(sw[delta_idx(pp, p)]);
    }
    size_t off = ((size_t)((h * 4 + pt) * 8 + ck)) * TILE_B + sw_off(row, c16);
    *reinterpret_cast<uint4*>(g_wh + off) = *reinterpret_cast<uint4*>(hb);
}

// ---------------- kernel 2: x -> blocked swizzled fp16 tiles ----------------
__global__ __launch_bounds__(256) void xsplit_kernel(const float* __restrict__ x) {
    __shared__ float s[64][65];
    const int t = threadIdx.x;
    const int c0 = blockIdx.x * 64;
    const int p0 = blockIdx.y * 64;
    const int b  = blockIdx.z;
    const int ck = blockIdx.y;      // 64 p' per ck chunk

#pragma unroll
    for (int it = 0; it < 16; it++) {
        int prow = it * 4 + (t >> 6);
        int cl   = t & 63;
        s[prow][cl] = x[((size_t)(b * SEQ) + p0 + prow) * CHAN + c0 + cl];
    }
    __syncthreads();

    const int cl = t >> 2;          // c local
    const int pq = t & 3;           // 16 p' each
    const int c  = c0 + cl;
    const int h  = c & 7;
    const int ch = c >> 3;
    const int n  = b * 64 + ch;
    const int nt = n >> 7;
    const int nrow = n & 127;
    const size_t tb = ((size_t)((h * 16 + nt) * 8 + ck)) * TILE_B;

#pragma unroll
    for (int g = 0; g < 2; g++) {
        int c16 = pq * 2 + g;
        __align__(16) __half hb[8];
#pragma unroll
        for (int j = 0; j < 8; j++)
            hb[j] = __float2half(s[c16 * 8 + j][cl]);
        *reinterpret_cast<uint4*>(g_xh + tb + sw_off(nrow, c16)) =
            *reinterpret_cast<uint4*>(hb);
    }
}

// ---------------- kernel 3: fp16 HMMA GEMM (R14 exact: 8 warps 32x64) ----------------
__global__ __launch_bounds__(256, 2) void gemm_kernel() {
    extern __shared__ __align__(16) unsigned char sm[];
    const uint32_t sb0 = smem_u32(sm);
    const int tid  = threadIdx.x;
    const int lane = tid & 31;
    const int wid  = tid >> 5;
    const int wm   = wid & 3;       // m-group: 32 p rows
    const int wn   = wid >> 2;      // n-group: 64 n cols
    const int pt = blockIdx.x, nt = blockIdx.y, h = blockIdx.z;
    const int p0 = pt * 128;
    const int n0 = nt * 128;

    const unsigned char* gA = g_wh + ((size_t)((h * 4 + pt) * 8)) * TILE_B;
    const unsigned char* gB = g_xh + ((size_t)((h * 16 + nt) * 8)) * TILE_B;

    if (tid == 0) {
#pragma unroll
        for (int st = 0; st < NSTAGE; st++) MB_INIT(sb0 + MBAR_OFF + st * 8, 1);
    }
    __syncthreads();
    if (tid == 0) {
#pragma unroll
        for (int st = 0; st < NSTAGE; st++) {
            uint32_t mb = sb0 + MBAR_OFF + st * 8;
            MB_EXPECT_TX(mb, STAGE_BYTES);
            CP_BULK(sb0 + st * STAGE_BYTES,          gA + st * TILE_B, TILE_B, mb);
            CP_BULK(sb0 + st * STAGE_BYTES + TILE_B, gB + st * TILE_B, TILE_B, mb);
        }
    }

    const int g  = lane >> 3, rr = lane & 7;
    const int a_row = wm * 32 + (g & 1) * 8 + rr;    // + mi*16
    const int a_cg  = g >> 1;                        // + 2*ks
    const int b_row = wn * 64 + (g >> 1) * 8 + rr;   // + bt*16
    const int b_cg  = g & 1;                         // + 2*ks

    float acc[2][8][4];
#pragma unroll
    for (int mi = 0; mi < 2; mi++)
#pragma unroll
        for (int ni = 0; ni < 8; ni++)
#pragma unroll
            for (int e = 0; e < 4; e++) acc[mi][ni][e] = 0.f;

    int st = 0, par = 0;
#pragma unroll 1
    for (int ck = 0; ck < 8; ck++) {
        const uint32_t mb = sb0 + MBAR_OFF + st * 8;
        MB_WAIT_PARITY(mb, par);
        const uint32_t sb = sb0 + st * STAGE_BYTES;

#pragma unroll
        for (int ks = 0; ks < 4; ks++) {
            uint32_t Af[2][4], Bf[4][4];
#pragma unroll
            for (int mi = 0; mi < 2; mi++) {
                int row = a_row + mi * 16;
                int c16 = 2 * ks + a_cg;
                ldsm_x4(Af[mi], sb + (uint32_t)sw_off(row, c16));
            }
#pragma unroll
            for (int bt = 0; bt < 4; bt++) {
                int row = b_row + bt * 16;
                int c16 = 2 * ks + b_cg;
                ldsm_x4(Bf[bt], sb + TILE_B + (uint32_t)sw_off(row, c16));
            }
#pragma unroll
            for (int mi = 0; mi < 2; mi++)
#pragma unroll
                for (int ni = 0; ni < 8; ni++)
                    mma_fp16(acc[mi][ni], Af[mi], &Bf[ni >> 1][(ni & 1) * 2]);
        }
        __syncthreads();   // all warps done with this stage buffer

        if (tid == 0 && ck + NSTAGE < 8) {
            MB_EXPECT_TX(mb, STAGE_BYTES);
            CP_BULK(sb,          gA + (ck + NSTAGE) * TILE_B, TILE_B, mb);
            CP_BULK(sb + TILE_B, gB + (ck + NSTAGE) * TILE_B, TILE_B, mb);
        }
        if (++st == NSTAGE) { st = 0; par ^= 1; }
    }

    // ---- epilogue: smem transpose then packed fp16 stores to g_outT[h][n][p] ----
    float* sf = reinterpret_cast<float*>(sm);   // [128 n][132 pad] fp32 (67.5KB < MBAR_OFF)
    {
        const int prl = wm * 32 + (lane >> 2);
        const int nll = wn * 64 + 2 * (lane & 3);
#pragma unroll
        for (int mi = 0; mi < 2; mi++)
#pragma unroll
            for (int ni = 0; ni < 8; ni++)
#pragma unroll
                for (int e = 0; e < 4; e++) {
                    int p_l = prl + mi * 16 + (e >> 1) * 8;
                    int n_l = nll + ni * 8 + (e & 1);
                    sf[n_l * 132 + p_l] = acc[mi][ni][e];
                }
    }
    __syncthreads();
    {
        const int n_l  = tid >> 1;
        const int half = tid & 1;
        const float* srcf = sf + n_l * 132 + half * 64;
        uint4* dst = reinterpret_cast<uint4*>(
            g_outT + ((size_t)(h * NPH) + n0 + n_l) * SEQ + p0 + half * 64);
#pragma unroll
        for (int i = 0; i < 8; i++) {
            float4 a = *reinterpret_cast<const float4*>(srcf + i * 8);
            float4 b4 = *reinterpret_cast<const float4*>(srcf + i * 8 + 4);
            __half2 h01 = __floats2half2_rn(a.x, a.y);
            __half2 h23 = __floats2half2_rn(a.z, a.w);
            __half2 h45 = __floats2half2_rn(b4.x, b4.y);
            __half2 h67 = __floats2half2_rn(b4.z, b4.w);
            uint4 pk;
            pk.x = *reinterpret_cast<uint32_t*>(&h01);
            pk.y = *reinterpret_cast<uint32_t*>(&h23);
            pk.z = *reinterpret_cast<uint32_t*>(&h45);
            pk.w = *reinterpret_cast<uint32_t*>(&h67);
            dst[i] = pk;
        }
    }
}

// ---------------- kernel 4: outT fp16 [h][n][p] -> out fp32 [b][p][c] ----------------
// Block tile: 64 p x 128 c (16KB smem) -> 1024 CTAs for occupancy.
__global__ __launch_bounds__(256) void untranspose_kernel(float* __restrict__ out) {
    __shared__ __align__(16) __half sh[128 * 64];   // 16KB
    const int t = threadIdx.x;
    const int p0 = blockIdx.x * 64;
    const int c0 = blockIdx.y * 128;
    const int b  = blockIdx.z;

    // load: 4 LDG.128/thread, coalesced 128B rows of outT; granule = 8 p halves
#pragma unroll
    for (int i = 0; i < 4; i++) {
        int vid = t + i * 256;          // 1024 granules
        int cl = vid >> 3, q = vid & 7;
        int c = c0 + cl;
        int h = c & 7, ch = c >> 3;
        uint4 v = *reinterpret_cast<const uint4*>(
            g_outT + ((size_t)(h * NPH) + b * 64 + ch) * SEQ + p0 + q * 8);
        int qs = q ^ ((cl >> 2) & 7);
        *reinterpret_cast<uint4*>(sh + cl * 64 + qs * 8) = v;
    }
    __syncthreads();

    // store: task = 4 c x 8 p; 4 LDS.128 + register transpose + 8 STG.128 (fp32)
    {
        int cq = t & 31, pq = t >> 5;   // 256 tasks
        int qs = pq ^ (cq & 7);         // ((4cq+j)>>2)&7 == cq&7 for j<4
        uint4 v[4];
#pragma unroll
        for (int j = 0; j < 4; j++)
            v[j] = *reinterpret_cast<const uint4*>(sh + (4 * cq + j) * 64 + qs * 8);
        const __half* hv = reinterpret_cast<const __half*>(v);
#pragma unroll
        for (int p = 0; p < 8; p++) {
            float4 o = make_float4(__half2float(hv[0 * 8 + p]),
                                   __half2float(hv[1 * 8 + p]),
                                   __half2float(hv[2 * 8 + p]),
                                   __half2float(hv[3 * 8 + p]));
            *reinterpret_cast<float4*>(
                out + ((size_t)(b * SEQ) + p0 + pq * 8 + p) * CHAN + c0 + 4 * cq) = o;
        }
    }
}

// ---------------- launch ----------------
extern "C" void kernel_launch(void* const* d_in, const int* in_sizes, int n_in,
                              void* d_out, int out_size) {
    const float* x = nullptr;
    const float* basis = nullptr;
    const float* kern = nullptr;
    for (int i = 0; i < n_in; i++) {
        if (in_sizes[i] == BATCH * SEQ * CHAN)      x     = (const float*)d_in[i];
        else if (in_sizes[i] == SEQ * 24)           basis = (const float*)d_in[i];
        else if (in_sizes[i] == 24 * NH)            kern  = (const float*)d_in[i];
    }
    float* out = (float*)d_out;

    cudaFuncSetAttribute(gemm_kernel,
                         cudaFuncAttributeMaxDynamicSharedMemorySize, GEMM_SMEM);

    wsplit_kernel<<<1024, 256>>>(basis, kern);
    xsplit_kernel<<<dim3(8, 8, 32), 256>>>(x);
    gemm_kernel<<<dim3(4, 16, NH), 256, GEMM_SMEM>>>();
    untranspose_kernel<<<dim3(8, 4, 32), 256>>>(out);
}